// round 1
// baseline (speedup 1.0000x reference)
#include <cuda_runtime.h>
#include <math.h>

#define NN 100000
#define FF 128
#define HH 16
#define CC 40
#define ALPHA 0.1f
#define BN_EPS 1e-5f

// ---------------- scratch (device globals; no allocation) ----------------
__device__ float g_tmps[NN * HH];   // (x@W1) * dinv[src-side]
__device__ float g_agg1[NN * HH];   // raw edge sum, conv1
__device__ float g_agg2[NN * HH];   // raw edge sum, conv2
__device__ float g_h[NN * HH];      // post-relu hidden
__device__ float g_h2s[NN * HH];    // post-hops hidden * dinv
__device__ float g_deg[NN];
__device__ float g_dinv[NN];
__device__ float g_stats[2 * HH];   // [sum | sumsq]
__device__ float g_scale[HH];
__device__ float g_shift[HH];

// ---------------- kernels ----------------

__global__ void k_zero(int n) {
    int total = n * HH;
    for (int i = blockIdx.x * blockDim.x + threadIdx.x; i < total;
         i += gridDim.x * blockDim.x) {
        g_agg1[i] = 0.0f;
        g_agg2[i] = 0.0f;
        if (i < n) g_deg[i] = 1.0f;      // self-loop
        if (i < 2 * HH) g_stats[i] = 0.0f;
    }
}

__global__ void k_deg(const int* __restrict__ dst, int ne) {
    int e = blockIdx.x * blockDim.x + threadIdx.x;
    if (e < ne) atomicAdd(&g_deg[dst[e]], 1.0f);
}

__global__ void k_dinv(int n) {
    int i = blockIdx.x * blockDim.x + threadIdx.x;
    if (i < n) g_dinv[i] = rsqrtf(g_deg[i]);
}

// x[N,128] @ W1[128,16], scaled by dinv[node] -> g_tmps
#define MM_TILE 64
__global__ void k_mm1(const float* __restrict__ x, const float* __restrict__ W1, int n) {
    __shared__ float xs[MM_TILE][FF + 1];   // +1 pad: conflict-free
    __shared__ float w1s[FF * HH];
    int t = threadIdx.x;                    // 64 threads
    int base = blockIdx.x * MM_TILE;

    #pragma unroll 4
    for (int i = t; i < FF * HH; i += MM_TILE) w1s[i] = W1[i];

    #pragma unroll 4
    for (int i = t; i < MM_TILE * FF; i += MM_TILE) {
        int node = i / FF, k = i % FF;
        float v = 0.0f;
        if (base + node < n) v = x[(size_t)(base + node) * FF + k];
        xs[node][k] = v;
    }
    __syncthreads();

    int node = base + t;
    if (node >= n) return;

    float acc[HH];
    #pragma unroll
    for (int j = 0; j < HH; j++) acc[j] = 0.0f;

    #pragma unroll 4
    for (int k = 0; k < FF; k++) {
        float xv = xs[t][k];
        const float4* wr = (const float4*)&w1s[k * HH];
        float4 w0 = wr[0], w1v = wr[1], w2v = wr[2], w3v = wr[3];
        acc[0]  += xv * w0.x;  acc[1]  += xv * w0.y;  acc[2]  += xv * w0.z;  acc[3]  += xv * w0.w;
        acc[4]  += xv * w1v.x; acc[5]  += xv * w1v.y; acc[6]  += xv * w1v.z; acc[7]  += xv * w1v.w;
        acc[8]  += xv * w2v.x; acc[9]  += xv * w2v.y; acc[10] += xv * w2v.z; acc[11] += xv * w2v.w;
        acc[12] += xv * w3v.x; acc[13] += xv * w3v.y; acc[14] += xv * w3v.z; acc[15] += xv * w3v.w;
    }

    float di = g_dinv[node];
    float4* op = (float4*)&g_tmps[(size_t)node * HH];
    op[0] = make_float4(acc[0]*di,  acc[1]*di,  acc[2]*di,  acc[3]*di);
    op[1] = make_float4(acc[4]*di,  acc[5]*di,  acc[6]*di,  acc[7]*di);
    op[2] = make_float4(acc[8]*di,  acc[9]*di,  acc[10]*di, acc[11]*di);
    op[3] = make_float4(acc[12]*di, acc[13]*di, acc[14]*di, acc[15]*di);
}

__device__ __forceinline__ void red_v4(float* p, float4 v) {
    asm volatile("red.global.add.v4.f32 [%0], {%1,%2,%3,%4};"
                 :: "l"(p), "f"(v.x), "f"(v.y), "f"(v.z), "f"(v.w) : "memory");
}

// edge aggregation: out[dst] += in[src] (16-wide), in already dinv[src]-scaled
template <int PASS>
__global__ void k_agg(const int* __restrict__ src, const int* __restrict__ dst, int ne) {
    int e = blockIdx.x * blockDim.x + threadIdx.x;
    if (e >= ne) return;
    const float* in = (PASS == 0) ? g_tmps : g_h2s;
    float* outp     = (PASS == 0) ? g_agg1 : g_agg2;
    int s = src[e], d = dst[e];
    const float4* ip = (const float4*)(in + (size_t)s * HH);
    float4 a0 = ip[0], a1 = ip[1], a2 = ip[2], a3 = ip[3];
    float* op = outp + (size_t)d * HH;
    red_v4(op + 0, a0);
    red_v4(op + 4, a1);
    red_v4(op + 8, a2);
    red_v4(op + 12, a3);
}

// h = relu(dinv*(agg1 + tmps) + b1), accumulate BN sum/sumsq
__global__ void k_post1(const float* __restrict__ b1, int n) {
    __shared__ float sb1[HH];
    __shared__ float sred[2 * HH];
    int t = threadIdx.x;
    if (t < HH) sb1[t] = b1[t];
    if (t < 2 * HH) sred[t] = 0.0f;
    __syncthreads();

    float ls[HH], lq[HH];
    #pragma unroll
    for (int j = 0; j < HH; j++) { ls[j] = 0.0f; lq[j] = 0.0f; }

    for (int node = blockIdx.x * blockDim.x + t; node < n;
         node += gridDim.x * blockDim.x) {
        float di = g_dinv[node];
        const float4* ap = (const float4*)&g_agg1[(size_t)node * HH];
        const float4* tp = (const float4*)&g_tmps[(size_t)node * HH];
        float4* hp = (float4*)&g_h[(size_t)node * HH];
        #pragma unroll
        for (int q = 0; q < 4; q++) {
            float4 a = ap[q], b = tp[q];
            float h0 = fmaxf(di * (a.x + b.x) + sb1[4*q+0], 0.0f);
            float h1 = fmaxf(di * (a.y + b.y) + sb1[4*q+1], 0.0f);
            float h2 = fmaxf(di * (a.z + b.z) + sb1[4*q+2], 0.0f);
            float h3 = fmaxf(di * (a.w + b.w) + sb1[4*q+3], 0.0f);
            hp[q] = make_float4(h0, h1, h2, h3);
            ls[4*q+0] += h0; lq[4*q+0] += h0 * h0;
            ls[4*q+1] += h1; lq[4*q+1] += h1 * h1;
            ls[4*q+2] += h2; lq[4*q+2] += h2 * h2;
            ls[4*q+3] += h3; lq[4*q+3] += h3 * h3;
        }
    }

    #pragma unroll
    for (int j = 0; j < HH; j++) {
        #pragma unroll
        for (int off = 16; off; off >>= 1) {
            ls[j] += __shfl_xor_sync(0xffffffffu, ls[j], off);
            lq[j] += __shfl_xor_sync(0xffffffffu, lq[j], off);
        }
    }
    if ((t & 31) == 0) {
        #pragma unroll
        for (int j = 0; j < HH; j++) {
            atomicAdd(&sred[j], ls[j]);
            atomicAdd(&sred[HH + j], lq[j]);
        }
    }
    __syncthreads();
    if (t < 2 * HH) atomicAdd(&g_stats[t], sred[t]);
}

__global__ void k_bnfin(const float* __restrict__ gamma,
                        const float* __restrict__ beta, float invN) {
    int j = threadIdx.x;
    if (j < HH) {
        float mean = g_stats[j] * invN;
        float var  = g_stats[HH + j] * invN - mean * mean;
        float sc   = gamma[j] * rsqrtf(var + BN_EPS);
        g_scale[j] = sc;
        g_shift[j] = beta[j] - mean * sc;
    }
}

// BN apply + 10 residual hops + pre-scale by dinv -> g_h2s
__global__ void k_hops(const float* __restrict__ Wl, const float* __restrict__ bl, int n) {
    __shared__ float swl[HH * HH];
    __shared__ float sbl[HH], ssc[HH], ssh[HH];
    int t = threadIdx.x;
    if (t < HH * HH) swl[t] = Wl[t];
    if (t < HH) { sbl[t] = bl[t]; ssc[t] = g_scale[t]; ssh[t] = g_shift[t]; }
    __syncthreads();

    int node = blockIdx.x * blockDim.x + t;
    if (node >= n) return;

    float v[HH];
    const float4* hp = (const float4*)&g_h[(size_t)node * HH];
    #pragma unroll
    for (int q = 0; q < 4; q++) {
        float4 a = hp[q];
        v[4*q+0] = a.x; v[4*q+1] = a.y; v[4*q+2] = a.z; v[4*q+3] = a.w;
    }
    #pragma unroll
    for (int j = 0; j < HH; j++) v[j] = v[j] * ssc[j] + ssh[j];

    #pragma unroll 1
    for (int it = 0; it < 10; it++) {
        float acc[HH];
        #pragma unroll
        for (int j = 0; j < HH; j++) acc[j] = sbl[j];
        #pragma unroll
        for (int k = 0; k < HH; k++) {
            float hk = v[k];
            const float4* wr = (const float4*)&swl[k * HH];
            #pragma unroll
            for (int q = 0; q < 4; q++) {
                float4 w = wr[q];
                acc[4*q+0] += hk * w.x;
                acc[4*q+1] += hk * w.y;
                acc[4*q+2] += hk * w.z;
                acc[4*q+3] += hk * w.w;
            }
        }
        #pragma unroll
        for (int j = 0; j < HH; j++)
            v[j] = ALPHA * fmaxf(acc[j], 0.0f) + (1.0f - ALPHA) * v[j];
    }

    float di = g_dinv[node];
    float4* op = (float4*)&g_h2s[(size_t)node * HH];
    #pragma unroll
    for (int q = 0; q < 4; q++)
        op[q] = make_float4(v[4*q+0]*di, v[4*q+1]*di, v[4*q+2]*di, v[4*q+3]*di);
}

// v = dinv*(agg2 + h2s); out = log_softmax(v @ W2 + b2)
__global__ void k_final(const float* __restrict__ W2, const float* __restrict__ b2,
                        float* __restrict__ out, int n) {
    __shared__ float sw2[HH * CC];
    __shared__ float sb2[CC];
    int t = threadIdx.x;
    for (int i = t; i < HH * CC; i += blockDim.x) sw2[i] = W2[i];
    if (t < CC) sb2[t] = b2[t];
    __syncthreads();

    int node = blockIdx.x * blockDim.x + t;
    if (node >= n) return;

    float di = g_dinv[node];
    float v[HH];
    const float4* ap = (const float4*)&g_agg2[(size_t)node * HH];
    const float4* hp = (const float4*)&g_h2s[(size_t)node * HH];
    #pragma unroll
    for (int q = 0; q < 4; q++) {
        float4 a = ap[q], h = hp[q];
        v[4*q+0] = di * (a.x + h.x);
        v[4*q+1] = di * (a.y + h.y);
        v[4*q+2] = di * (a.z + h.z);
        v[4*q+3] = di * (a.w + h.w);
    }

    float o[CC];
    #pragma unroll
    for (int j = 0; j < CC; j++) o[j] = sb2[j];
    #pragma unroll
    for (int k = 0; k < HH; k++) {
        float hk = v[k];
        const float4* wr = (const float4*)&sw2[k * CC];
        #pragma unroll
        for (int q = 0; q < CC / 4; q++) {
            float4 w = wr[q];
            o[4*q+0] += hk * w.x;
            o[4*q+1] += hk * w.y;
            o[4*q+2] += hk * w.z;
            o[4*q+3] += hk * w.w;
        }
    }

    float m = o[0];
    #pragma unroll
    for (int j = 1; j < CC; j++) m = fmaxf(m, o[j]);
    float s = 0.0f;
    #pragma unroll
    for (int j = 0; j < CC; j++) s += expf(o[j] - m);
    float lse = m + logf(s);

    float4* op4 = (float4*)&out[(size_t)node * CC];
    #pragma unroll
    for (int q = 0; q < CC / 4; q++)
        op4[q] = make_float4(o[4*q+0]-lse, o[4*q+1]-lse, o[4*q+2]-lse, o[4*q+3]-lse);
}

// ---------------- launch ----------------
extern "C" void kernel_launch(void* const* d_in, const int* in_sizes, int n_in,
                              void* d_out, int out_size) {
    const float* x     = (const float*)d_in[0];
    const int*   src   = (const int*)d_in[1];
    const int*   dst   = (const int*)d_in[2];
    const float* W1    = (const float*)d_in[3];
    const float* b1    = (const float*)d_in[4];
    const float* gamma = (const float*)d_in[5];
    const float* beta  = (const float*)d_in[6];
    const float* Wl    = (const float*)d_in[7];
    const float* bl    = (const float*)d_in[8];
    const float* W2    = (const float*)d_in[9];
    const float* b2    = (const float*)d_in[10];
    float* out = (float*)d_out;

    int n  = in_sizes[0] / FF;
    int ne = in_sizes[1];
    if (n > NN) n = NN;

    int nb256 = (n + 255) / 256;
    int eb256 = (ne + 255) / 256;

    k_zero<<<2048, 256>>>(n);
    k_deg<<<eb256, 256>>>(dst, ne);
    k_dinv<<<nb256, 256>>>(n);
    k_mm1<<<(n + MM_TILE - 1) / MM_TILE, MM_TILE>>>(x, W1, n);
    k_agg<0><<<eb256, 256>>>(src, dst, ne);
    k_post1<<<256, 256>>>(b1, n);
    k_bnfin<<<1, 32>>>(gamma, beta, 1.0f / (float)n);
    k_hops<<<nb256, 256>>>(Wl, bl, n);
    k_agg<1><<<eb256, 256>>>(src, dst, ne);
    k_final<<<nb256, 256>>>(W2, b2, out, n);
}